// round 5
// baseline (speedup 1.0000x reference)
#include <cuda_runtime.h>
#include <cuda_bf16.h>

// SSIM loss, fused single-pass tiled kernel + fused deterministic reduction.
// pred, target: (16,3,512,512) f32.  Output: scalar f32 = 1 - mean(ssim_map).
// Gaussian 11x11 sigma=1.5, separable; weights as FFMA immediates (rt=1 on sm_103a).

#define IMG_H 512
#define IMG_W 512
#define NCHAN 48
#define TW 64
#define TH 32
#define HALO 5
#define INW 74
#define INH 42
#define SPS 75              // sP/sQ row stride (floats)
#define SHS 65              // sH row stride (floats)
#define GX 8
#define GY 16
#define NPART (GX*GY*NCHAN) // 6144
#define NPIX (16.0*3.0*512.0*512.0)

#define SP_OFF 0
#define SQ_OFF (INH*SPS)            // 3150
#define SH_OFF (2*INH*SPS)          // 6300
#define SH_MAP (INH*SHS)            // 2730
#define SMEM_FLOATS (SH_OFF + 5*SH_MAP)   // 19950
#define SMEM_BYTES (SMEM_FLOATS*4)        // 79800

// compile-time weights -> FFMA-imm in SASS (rt_SMSP=1 vs 2 for 3-reg form)
__device__ constexpr float WC[11] = {
    0.00102838f, 0.00759876f, 0.03600077f, 0.10936068f, 0.21300557f,
    0.26601170f,
    0.21300557f, 0.10936068f, 0.03600077f, 0.00759876f, 0.00102838f
};

__device__ float g_part[NPART];
__device__ unsigned int g_count;   // zero-initialized; reset by last block each call

__global__ __launch_bounds__(512)
void ssim_tile_kernel(const float* __restrict__ pred,
                      const float* __restrict__ targ,
                      float* __restrict__ out)
{
    extern __shared__ float sm[];
    float* sP = sm + SP_OFF;
    float* sQ = sm + SQ_OFF;
    __shared__ float warpsum[16];
    __shared__ bool  is_last;

    const int tid = threadIdx.x;
    const int bx = blockIdx.x, by = blockIdx.y, bz = blockIdx.z;

    const float* __restrict__ p = pred + (size_t)bz * (IMG_H * IMG_W);
    const float* __restrict__ q = targ + (size_t)bz * (IMG_H * IMG_W);

    const int gx0 = bx * TW - HALO;
    const int gy0 = by * TH - HALO;

    // ---- load 74x42 halo tiles of pred & target (zero-padded) ----
    for (int i = tid; i < INH * INW; i += 512) {
        int r = i / INW, c = i - r * INW;
        int gy = gy0 + r, gx = gx0 + c;
        float pv = 0.f, qv = 0.f;
        if ((unsigned)gy < IMG_H && (unsigned)gx < IMG_W) {
            int o = gy * IMG_W + gx;
            pv = p[o]; qv = q[o];
        }
        sP[r * SPS + c] = pv;
        sQ[r * SPS + c] = qv;
    }
    __syncthreads();

    // ---- horizontal pass: 42 rows x 16 groups of 4 cols, 5 maps ----
    // maps: 0=x, 1=y, 2=x*x, 3=y*y, 4=x*y (products formed on the fly)
    for (int t = tid; t < INH * 16; t += 512) {
        int r  = t >> 4;
        int cg = (t & 15) << 2;      // output col base 0..60

        float pv[14], qv[14];
        #pragma unroll
        for (int j = 0; j < 14; j++) {
            pv[j] = sP[r * SPS + cg + j];
            qv[j] = sQ[r * SPS + cg + j];
        }

        float ax[4]  = {0,0,0,0}, ay[4]  = {0,0,0,0};
        float axx[4] = {0,0,0,0}, ayy[4] = {0,0,0,0}, axy[4] = {0,0,0,0};
        #pragma unroll
        for (int j = 0; j < 14; j++) {
            float pp = pv[j] * pv[j];
            float qq = qv[j] * qv[j];
            float pq = pv[j] * qv[j];
            #pragma unroll
            for (int k = 0; k < 4; k++) {
                int tap = j - k;
                if (tap >= 0 && tap < 11) {
                    ax[k]  = fmaf(WC[tap], pv[j], ax[k]);
                    ay[k]  = fmaf(WC[tap], qv[j], ay[k]);
                    axx[k] = fmaf(WC[tap], pp, axx[k]);
                    ayy[k] = fmaf(WC[tap], qq, ayy[k]);
                    axy[k] = fmaf(WC[tap], pq, axy[k]);
                }
            }
        }
        float* sH = sm + SH_OFF + r * SHS + cg;
        #pragma unroll
        for (int k = 0; k < 4; k++) {
            sH[0*SH_MAP + k] = ax[k];
            sH[1*SH_MAP + k] = ay[k];
            sH[2*SH_MAP + k] = axx[k];
            sH[3*SH_MAP + k] = ayy[k];
            sH[4*SH_MAP + k] = axy[k];
        }
    }
    __syncthreads();

    // ---- vertical pass + SSIM pointwise: thread -> 4 rows of one col ----
    const int tx = tid & 63;
    const int y0 = (tid >> 6) << 2;   // 0,4,...,28

    float res[5][4];
    #pragma unroll
    for (int m = 0; m < 5; m++) {
        const float* sHm = sm + SH_OFF + m * SH_MAP;
        float v[14];
        #pragma unroll
        for (int j = 0; j < 14; j++)
            v[j] = sHm[(y0 + j) * SHS + tx];
        #pragma unroll
        for (int k = 0; k < 4; k++) {
            float a = 0.f;
            #pragma unroll
            for (int tap = 0; tap < 11; tap++)
                a = fmaf(WC[tap], v[k + tap], a);
            res[m][k] = a;
        }
    }

    const float C1 = 1e-4f, C2 = 9e-4f;
    float local = 0.f;
    #pragma unroll
    for (int k = 0; k < 4; k++) {
        float mx = res[0][k], my = res[1][k];
        float mxs = mx * mx, mys = my * my, mxy = mx * my;
        float sx  = res[2][k] - mxs;
        float sy  = res[3][k] - mys;
        float sxy = res[4][k] - mxy;
        float num = (2.f * mxy + C1) * (2.f * sxy + C2);
        float den = (mxs + mys + C1) * (sx + sy + C2);
        local += num / den;
    }

    // ---- block reduction ----
    #pragma unroll
    for (int o = 16; o > 0; o >>= 1)
        local += __shfl_down_sync(0xFFFFFFFFu, local, o);
    if ((tid & 31) == 0) warpsum[tid >> 5] = local;
    __syncthreads();
    if (tid == 0) {
        float s = 0.f;
        #pragma unroll
        for (int i = 0; i < 16; i++) s += warpsum[i];
        g_part[(bz * GY + by) * GX + bx] = s;
        __threadfence();
        unsigned old = atomicAdd(&g_count, 1u);
        is_last = (old == NPART - 1);
    }
    __syncthreads();

    // ---- last block: deterministic fixed-order final reduction ----
    if (is_last) {
        double s = 0.0;
        for (int i = tid; i < NPART; i += 512)
            s += (double)__ldcg(&g_part[i]);
        double* sd = (double*)sm;     // reuse dynamic smem (tile phase done)
        __syncthreads();
        sd[tid] = s;
        __syncthreads();
        for (int o = 256; o > 0; o >>= 1) {
            if (tid < o) sd[tid] += sd[tid + o];
            __syncthreads();
        }
        if (tid == 0) {
            out[0] = (float)(1.0 - sd[0] / NPIX);
            g_count = 0;              // reset for next replay (determinism)
        }
    }
}

extern "C" void kernel_launch(void* const* d_in, const int* in_sizes, int n_in,
                              void* d_out, int out_size)
{
    const float* pred = (const float*)d_in[0];
    const float* targ = (const float*)d_in[1];
    float* out = (float*)d_out;

    cudaFuncSetAttribute(ssim_tile_kernel,
                         cudaFuncAttributeMaxDynamicSharedMemorySize, SMEM_BYTES);

    dim3 grid(GX, GY, NCHAN);    // 8x16 tiles of 64x32, 48 channel-images
    ssim_tile_kernel<<<grid, 512, SMEM_BYTES>>>(pred, targ, out);
}

// round 6
// speedup vs baseline: 1.5364x; 1.5364x over previous
#include <cuda_runtime.h>
#include <cuda_bf16.h>

// SSIM loss: persistent 32x256 column-strip kernel, separable 11x11 Gaussian,
// rolling H-conv buffer (no vertical halo recompute), fused deterministic reduce.
// pred,target: (16,3,512,512) f32 -> scalar f32 = 1 - mean(ssim_map).

#define IMG_H 512
#define IMG_W 512
#define TW 32
#define CHUNK 32
#define NCHUNK 8            // 8*32 = 256 rows per strip
#define INW 42              // TW + 10
#define SPS 43              // input buffer stride (conflict-free)
#define SHS 33              // sH stride (conflict-free)
#define SH_MAP (42*SHS)     // 1386 floats per map
#define GXB 16
#define GYB 2
#define NCH 48
#define NPART (GXB*GYB*NCH) // 1536
#define NPIX (16.0*3.0*512.0*512.0)

// compile-time weights -> FFMA with immediate multiplier (rt_SMSP=1)
__device__ constexpr float WC[11] = {
    0.00102838f, 0.00759876f, 0.03600077f, 0.10936068f, 0.21300557f,
    0.26601170f,
    0.21300557f, 0.10936068f, 0.03600077f, 0.00759876f, 0.00102838f
};

__device__ float g_part[NPART];
__device__ unsigned int g_count;   // zero-init; last block resets each call

__global__ __launch_bounds__(256, 5)
void ssim_strip_kernel(const float* __restrict__ pred,
                       const float* __restrict__ targ,
                       float* __restrict__ out)
{
    __shared__ float sP[42 * SPS];          // input rows (up to 42)
    __shared__ float sQ[42 * SPS];
    __shared__ float sH[5 * SH_MAP];        // H-conv rows: window of 42
    __shared__ float warpsum[8];
    __shared__ bool  is_last;

    const int tid = threadIdx.x;
    const int bx = blockIdx.x, by = blockIdx.y, bz = blockIdx.z;

    const float* __restrict__ p = pred + (size_t)bz * (IMG_H * IMG_W);
    const float* __restrict__ q = targ + (size_t)bz * (IMG_H * IMG_W);

    const int gx0 = bx * TW - 5;            // leftmost input col (rel 0)
    const int ybase = by * (CHUNK * NCHUNK);

    float local = 0.f;

    for (int ch = 0; ch < NCHUNK; ch++) {
        // how many new H rows this chunk: 42 for chunk 0, else 32
        const int nrows = (ch == 0) ? 42 : 32;
        // absolute image row of input-buffer row 0 for this chunk
        const int gyb = (ch == 0) ? (ybase - 5) : (ybase + ch * CHUNK + 5);
        // sH destination row for input-buffer row 0
        const int hdst0 = (ch == 0) ? 0 : 10;

        __syncthreads();   // prior V-pass (and prior H reads) complete

        // ---- roll sH: copy rows 32..41 -> 0..9 (all 5 maps) ----
        if (ch > 0) {
            for (int i = tid; i < 10 * TW * 5; i += 256) {
                int m = i / (10 * TW);
                int rem = i - m * (10 * TW);
                int r = rem >> 5;
                int c = rem & 31;
                sH[m * SH_MAP + r * SHS + c] =
                    sH[m * SH_MAP + (32 + r) * SHS + c];
            }
        }

        // ---- load new input rows (zero-padded at borders) ----
        for (int i = tid; i < nrows * INW; i += 256) {
            int r = i / INW, c = i - r * INW;
            int gy = gyb + r, gx = gx0 + c;
            float pv = 0.f, qv = 0.f;
            if ((unsigned)gy < IMG_H && (unsigned)gx < IMG_W) {
                int o = gy * IMG_W + gx;
                pv = p[o]; qv = q[o];
            }
            sP[r * SPS + c] = pv;
            sQ[r * SPS + c] = qv;
        }
        __syncthreads();   // copy + loads visible

        // ---- horizontal pass: nrows x 8 groups of 4 cols, 5 maps ----
        for (int t = tid; t < nrows * 8; t += 256) {
            int r  = t >> 3;
            int cg = (t & 7) << 2;

            float ax0=0,ax1=0,ax2=0,ax3=0;
            float ay0=0,ay1=0,ay2=0,ay3=0;
            float bx0=0,bx1=0,bx2=0,bx3=0;
            float by0=0,by1=0,by2=0,by3=0;
            float cx0=0,cx1=0,cx2=0,cx3=0;
            const float* rp = sP + r * SPS + cg;
            const float* rq = sQ + r * SPS + cg;
            #pragma unroll
            for (int j = 0; j < 14; j++) {
                float pv = rp[j];
                float qv = rq[j];
                float pp = pv * pv, qq = qv * qv, pq = pv * qv;
                if (j < 11)          { float w = WC[j];
                    ax0=fmaf(w,pv,ax0); ay0=fmaf(w,qv,ay0);
                    bx0=fmaf(w,pp,bx0); by0=fmaf(w,qq,by0); cx0=fmaf(w,pq,cx0); }
                if (j>=1 && j<12)    { float w = WC[j-1];
                    ax1=fmaf(w,pv,ax1); ay1=fmaf(w,qv,ay1);
                    bx1=fmaf(w,pp,bx1); by1=fmaf(w,qq,by1); cx1=fmaf(w,pq,cx1); }
                if (j>=2 && j<13)    { float w = WC[j-2];
                    ax2=fmaf(w,pv,ax2); ay2=fmaf(w,qv,ay2);
                    bx2=fmaf(w,pp,bx2); by2=fmaf(w,qq,by2); cx2=fmaf(w,pq,cx2); }
                if (j>=3)            { float w = WC[j-3];
                    ax3=fmaf(w,pv,ax3); ay3=fmaf(w,qv,ay3);
                    bx3=fmaf(w,pp,bx3); by3=fmaf(w,qq,by3); cx3=fmaf(w,pq,cx3); }
            }
            float* h = sH + (hdst0 + r) * SHS + cg;
            h[0*SH_MAP+0]=ax0; h[0*SH_MAP+1]=ax1; h[0*SH_MAP+2]=ax2; h[0*SH_MAP+3]=ax3;
            h[1*SH_MAP+0]=ay0; h[1*SH_MAP+1]=ay1; h[1*SH_MAP+2]=ay2; h[1*SH_MAP+3]=ay3;
            h[2*SH_MAP+0]=bx0; h[2*SH_MAP+1]=bx1; h[2*SH_MAP+2]=bx2; h[2*SH_MAP+3]=bx3;
            h[3*SH_MAP+0]=by0; h[3*SH_MAP+1]=by1; h[3*SH_MAP+2]=by2; h[3*SH_MAP+3]=by3;
            h[4*SH_MAP+0]=cx0; h[4*SH_MAP+1]=cx1; h[4*SH_MAP+2]=cx2; h[4*SH_MAP+3]=cx3;
        }
        __syncthreads();   // sH rows 0..41 valid for this chunk's window

        // ---- vertical pass + SSIM pointwise: thread -> 4 rows of one col ----
        {
            const int tx = tid & 31;
            const int y0 = (tid >> 5) << 2;     // 0,4,...,28
            float acc[5][4];
            #pragma unroll
            for (int m = 0; m < 5; m++)
                #pragma unroll
                for (int k = 0; k < 4; k++) acc[m][k] = 0.f;

            const float* basev = sH + y0 * SHS + tx;
            #pragma unroll
            for (int jj = 0; jj < 14; jj++) {
                float v0 = basev[0*SH_MAP + jj*SHS];
                float v1 = basev[1*SH_MAP + jj*SHS];
                float v2 = basev[2*SH_MAP + jj*SHS];
                float v3 = basev[3*SH_MAP + jj*SHS];
                float v4 = basev[4*SH_MAP + jj*SHS];
                #pragma unroll
                for (int k = 0; k < 4; k++) {
                    int tap = jj - k;
                    if (tap >= 0 && tap < 11) {
                        float w = WC[tap];
                        acc[0][k] = fmaf(w, v0, acc[0][k]);
                        acc[1][k] = fmaf(w, v1, acc[1][k]);
                        acc[2][k] = fmaf(w, v2, acc[2][k]);
                        acc[3][k] = fmaf(w, v3, acc[3][k]);
                        acc[4][k] = fmaf(w, v4, acc[4][k]);
                    }
                }
            }

            const float C1 = 1e-4f, C2 = 9e-4f;
            #pragma unroll
            for (int k = 0; k < 4; k++) {
                float mx = acc[0][k], my = acc[1][k];
                float mxs = mx*mx, mys = my*my, mxy = mx*my;
                float sx  = acc[2][k] - mxs;
                float sy  = acc[3][k] - mys;
                float sxy = acc[4][k] - mxy;
                float num = (2.f*mxy + C1) * (2.f*sxy + C2);
                float den = (mxs + mys + C1) * (sx + sy + C2);
                local += num / den;
            }
        }
    }

    // ---- block reduction ----
    #pragma unroll
    for (int o = 16; o > 0; o >>= 1)
        local += __shfl_down_sync(0xFFFFFFFFu, local, o);
    if ((tid & 31) == 0) warpsum[tid >> 5] = local;
    __syncthreads();
    if (tid == 0) {
        float s = 0.f;
        #pragma unroll
        for (int i = 0; i < 8; i++) s += warpsum[i];
        g_part[(bz * GYB + by) * GXB + bx] = s;
        __threadfence();
        unsigned old = atomicAdd(&g_count, 1u);
        is_last = (old == NPART - 1);
    }
    __syncthreads();

    // ---- last block: deterministic fixed-order final reduction ----
    if (is_last) {
        double s = 0.0;
        for (int i = tid; i < NPART; i += 256)
            s += (double)__ldcg(&g_part[i]);
        double* sd = (double*)sP;      // reuse smem (tile phase done)
        sd[tid] = s;
        __syncthreads();
        for (int o = 128; o > 0; o >>= 1) {
            if (tid < o) sd[tid] += sd[tid + o];
            __syncthreads();
        }
        if (tid == 0) {
            out[0] = (float)(1.0 - sd[0] / NPIX);
            g_count = 0;               // reset for next replay
        }
    }
}

extern "C" void kernel_launch(void* const* d_in, const int* in_sizes, int n_in,
                              void* d_out, int out_size)
{
    const float* pred = (const float*)d_in[0];
    const float* targ = (const float*)d_in[1];
    float* out = (float*)d_out;

    dim3 grid(GXB, GYB, NCH);   // 16 x-strips, 2 y-halves, 48 channel-images
    ssim_strip_kernel<<<grid, 256>>>(pred, targ, out);
}

// round 10
// speedup vs baseline: 1.7730x; 1.1540x over previous
#include <cuda_runtime.h>
#include <cuda_bf16.h>

// SSIM loss: persistent 32x256 column-strip kernel, separable 11x11 Gaussian.
// f32x2 packed FMA (FFMA2) on paired maps (x,y) and (x^2,y^2); xy scalar.
// Rolling H-conv window; fused deterministic last-block reduction.
// pred,target: (16,3,512,512) f32 -> scalar f32 = 1 - mean(ssim_map).

typedef unsigned long long ull;

#define IMG_H 512
#define IMG_W 512
#define TW 32
#define CHUNK 32
#define NCHUNK 8            // 8*32 = 256 rows per strip
#define INW 42              // TW + 10
#define SPS 43              // sPQ stride (in 8B float2 units) - conflict-free
#define SHS 33              // sH stride - conflict-free
#define GXB 16
#define GYB 2
#define NCH 48
#define NPART (GXB*GYB*NCH) // 1536
#define NPIX (16.0*3.0*512.0*512.0)

__device__ constexpr float WC[11] = {
    0.00102838f, 0.00759876f, 0.03600077f, 0.10936068f, 0.21300557f,
    0.26601170f,
    0.21300557f, 0.10936068f, 0.03600077f, 0.00759876f, 0.00102838f
};

__device__ __forceinline__ ull pack2(float lo, float hi) {
    ull r; asm("mov.b64 %0, {%1, %2};" : "=l"(r) : "f"(lo), "f"(hi)); return r;
}
__device__ __forceinline__ float2 unpack2(ull v) {
    float2 t; asm("mov.b64 {%0, %1}, %2;" : "=f"(t.x), "=f"(t.y) : "l"(v)); return t;
}
__device__ __forceinline__ ull fma2(ull a, ull b, ull c) {
    ull d; asm("fma.rn.f32x2 %0, %1, %2, %3;" : "=l"(d) : "l"(a), "l"(b), "l"(c)); return d;
}
__device__ __forceinline__ ull mul2(ull a, ull b) {
    ull d; asm("mul.rn.f32x2 %0, %1, %2;" : "=l"(d) : "l"(a), "l"(b)); return d;
}
#define W2(tap) pack2(WC[tap], WC[tap])

__device__ float g_part[NPART];
__device__ unsigned int g_count;   // zero-init; last block resets each call

__global__ __launch_bounds__(256, 5)
void ssim_strip_kernel(const float* __restrict__ pred,
                       const float* __restrict__ targ,
                       float* __restrict__ out)
{
    __shared__ ull   sPQ[42 * SPS];     // packed (p,q) input rows
    __shared__ ull   sH01[42 * SHS];    // packed (hx, hy)
    __shared__ ull   sH23[42 * SHS];    // packed (hxx, hyy)
    __shared__ float sH4 [42 * SHS];    // hxy
    __shared__ float warpsum[8];
    __shared__ bool  is_last;

    const int tid = threadIdx.x;
    const int bx = blockIdx.x, by = blockIdx.y, bz = blockIdx.z;

    const float* __restrict__ p = pred + (size_t)bz * (IMG_H * IMG_W);
    const float* __restrict__ q = targ + (size_t)bz * (IMG_H * IMG_W);

    const int gx0 = bx * TW - 5;
    const int ybase = by * (CHUNK * NCHUNK);
    const bool xin = (gx0 >= 0) && (gx0 + INW <= IMG_W);

    float local = 0.f;

    for (int ch = 0; ch < NCHUNK; ch++) {
        const int nrows = (ch == 0) ? 42 : 32;
        const int gyb   = (ch == 0) ? (ybase - 5) : (ybase + ch * CHUNK + 5);
        const int hdst0 = (ch == 0) ? 0 : 10;

        __syncthreads();   // prior V-pass / H reads complete

        // ---- roll sH: rows 32..41 -> 0..9 (all maps) ----
        if (ch > 0) {
            for (int i = tid; i < 10 * TW; i += 256) {
                int r = i >> 5, c = i & 31;
                int d = r * SHS + c, s = (32 + r) * SHS + c;
                sH01[d] = sH01[s];
                sH23[d] = sH23[s];
                sH4[d]  = sH4[s];
            }
        }

        // ---- load new input rows (packed), interior fast path ----
        if (xin && gyb >= 0 && gyb + nrows <= IMG_H) {
            const float* pb = p + gyb * IMG_W + gx0;
            const float* qb = q + gyb * IMG_W + gx0;
            for (int i = tid; i < nrows * INW; i += 256) {
                int r = i / INW, c = i - r * INW;
                int o = r * IMG_W + c;
                sPQ[r * SPS + c] = pack2(pb[o], qb[o]);
            }
        } else {
            for (int i = tid; i < nrows * INW; i += 256) {
                int r = i / INW, c = i - r * INW;
                int gy = gyb + r, gx = gx0 + c;
                float pv = 0.f, qv = 0.f;
                if ((unsigned)gy < IMG_H && (unsigned)gx < IMG_W) {
                    int o = gy * IMG_W + gx;
                    pv = p[o]; qv = q[o];
                }
                sPQ[r * SPS + c] = pack2(pv, qv);
            }
        }
        __syncthreads();

        // ---- horizontal pass ----
        // lane map: r = 4*(t>>5) + (t&3), cg = ((t&31)>>2)*4  (conflict-free LDS.64)
        const int ntask = ((nrows + 3) >> 2) << 5;   // 256 (steady) or 352 (ch 0)
        for (int t = tid; t < ntask; t += 256) {
            int r  = ((t >> 5) << 2) + (t & 3);
            if (r >= nrows) continue;
            int cg = (t & 31) & ~3;                  // 0,4,...,28

            ull a01[4], a23[4]; float a4[4];
            #pragma unroll
            for (int k = 0; k < 4; k++) { a01[k] = 0; a23[k] = 0; a4[k] = 0.f; }

            const ull* rp = sPQ + r * SPS + cg;
            #pragma unroll
            for (int j = 0; j < 14; j++) {
                ull pq = rp[j];
                float2 t2 = unpack2(pq);
                ull prod = mul2(pq, pq);             // (p*p, q*q)
                float s = t2.x * t2.y;               // p*q
                #pragma unroll
                for (int k = 0; k < 4; k++) {
                    int tap = j - k;
                    if (tap >= 0 && tap < 11) {
                        ull w2 = W2(tap);
                        a01[k] = fma2(w2, pq,   a01[k]);
                        a23[k] = fma2(w2, prod, a23[k]);
                        a4[k]  = fmaf(WC[tap], s, a4[k]);
                    }
                }
            }
            int hb = (hdst0 + r) * SHS + cg;
            #pragma unroll
            for (int k = 0; k < 4; k++) {
                sH01[hb + k] = a01[k];
                sH23[hb + k] = a23[k];
                sH4[hb + k]  = a4[k];
            }
        }
        __syncthreads();

        // ---- vertical pass + SSIM pointwise: thread -> 4 rows of one col ----
        {
            const int tx = tid & 31;
            const int y0 = (tid >> 5) << 2;          // 0,4,...,28

            ull acc01[4], acc23[4]; float acc4[4];
            #pragma unroll
            for (int k = 0; k < 4; k++) { acc01[k] = 0; acc23[k] = 0; acc4[k] = 0.f; }

            #pragma unroll
            for (int jj = 0; jj < 14; jj++) {
                int rb = (y0 + jj) * SHS + tx;
                ull v01 = sH01[rb];
                ull v23 = sH23[rb];
                float v4 = sH4[rb];
                #pragma unroll
                for (int k = 0; k < 4; k++) {
                    int tap = jj - k;
                    if (tap >= 0 && tap < 11) {
                        ull w2 = W2(tap);
                        acc01[k] = fma2(w2, v01, acc01[k]);
                        acc23[k] = fma2(w2, v23, acc23[k]);
                        acc4[k]  = fmaf(WC[tap], v4, acc4[k]);
                    }
                }
            }

            const float C1 = 1e-4f, C2 = 9e-4f;
            #pragma unroll
            for (int k = 0; k < 4; k++) {
                float2 m = unpack2(acc01[k]);        // (mu_x, mu_y)
                float2 e = unpack2(acc23[k]);        // (E[x^2], E[y^2])
                float mx = m.x, my = m.y;
                float mxs = mx * mx, mys = my * my, mxy = mx * my;
                float sx  = e.x - mxs;
                float sy  = e.y - mys;
                float sxy = acc4[k] - mxy;
                float num = (2.f * mxy + C1) * (2.f * sxy + C2);
                float den = (mxs + mys + C1) * (sx + sy + C2);
                local += num / den;
            }
        }
    }

    // ---- block reduction ----
    #pragma unroll
    for (int o = 16; o > 0; o >>= 1)
        local += __shfl_down_sync(0xFFFFFFFFu, local, o);
    if ((tid & 31) == 0) warpsum[tid >> 5] = local;
    __syncthreads();
    if (tid == 0) {
        float s = 0.f;
        #pragma unroll
        for (int i = 0; i < 8; i++) s += warpsum[i];
        g_part[(bz * GYB + by) * GXB + bx] = s;
        __threadfence();
        unsigned old = atomicAdd(&g_count, 1u);
        is_last = (old == NPART - 1);
    }
    __syncthreads();

    // ---- last block: deterministic fixed-order final reduction ----
    if (is_last) {
        double s = 0.0;
        for (int i = tid; i < NPART; i += 256)
            s += (double)__ldcg(&g_part[i]);
        double* sd = (double*)sPQ;     // reuse smem (tile phase done)
        sd[tid] = s;
        __syncthreads();
        for (int o = 128; o > 0; o >>= 1) {
            if (tid < o) sd[tid] += sd[tid + o];
            __syncthreads();
        }
        if (tid == 0) {
            out[0] = (float)(1.0 - sd[0] / NPIX);
            g_count = 0;               // reset for next replay
        }
    }
}

extern "C" void kernel_launch(void* const* d_in, const int* in_sizes, int n_in,
                              void* d_out, int out_size)
{
    const float* pred = (const float*)d_in[0];
    const float* targ = (const float*)d_in[1];
    float* out = (float*)d_out;

    dim3 grid(GXB, GYB, NCH);   // 16 x-strips, 2 y-halves, 48 channel-images
    ssim_strip_kernel<<<grid, 256>>>(pred, targ, out);
}

// round 14
// speedup vs baseline: 2.1482x; 1.2117x over previous
#include <cuda_runtime.h>
#include <cuda_bf16.h>

// SSIM loss via (u,v)=(x+y,x-y) rotation: only 4 separable 11x11 convolutions
// (u, v, u^2, v^2), all packed as f32x2 FFMA2 chains. Persistent 32x256 strips,
// rolling H-window, fused deterministic last-block reduction.
// pred,target: (16,3,512,512) f32 -> scalar f32 = 1 - mean(ssim_map).

typedef unsigned long long ull;

#define IMG_H 512
#define IMG_W 512
#define TW 32
#define CHUNK 32
#define NCHUNK 8            // 8*32 = 256 rows per strip
#define INW 42              // TW + 10
#define SPS 43              // sUV stride (8B units) - conflict-free
#define SHS 33              // sH stride - conflict-free
#define GXB 16
#define GYB 2
#define NCH 48
#define NPART (GXB*GYB*NCH) // 1536
#define NPIX (16.0*3.0*512.0*512.0)

__device__ constexpr float WC[11] = {
    0.00102838f, 0.00759876f, 0.03600077f, 0.10936068f, 0.21300557f,
    0.26601170f,
    0.21300557f, 0.10936068f, 0.03600077f, 0.00759876f, 0.00102838f
};

__device__ __forceinline__ ull pack2(float lo, float hi) {
    ull r; asm("mov.b64 %0, {%1, %2};" : "=l"(r) : "f"(lo), "f"(hi)); return r;
}
__device__ __forceinline__ float2 unpack2(ull v) {
    float2 t; asm("mov.b64 {%0, %1}, %2;" : "=f"(t.x), "=f"(t.y) : "l"(v)); return t;
}
__device__ __forceinline__ ull fma2(ull a, ull b, ull c) {
    ull d; asm("fma.rn.f32x2 %0, %1, %2, %3;" : "=l"(d) : "l"(a), "l"(b), "l"(c)); return d;
}
__device__ __forceinline__ ull mul2(ull a, ull b) {
    ull d; asm("mul.rn.f32x2 %0, %1, %2;" : "=l"(d) : "l"(a), "l"(b)); return d;
}
#define W2(tap) pack2(WC[tap], WC[tap])

__device__ float g_part[NPART];
__device__ unsigned int g_count;   // zero-init; last block resets each call

__global__ __launch_bounds__(256, 6)
void ssim_strip_kernel(const float* __restrict__ pred,
                       const float* __restrict__ targ,
                       float* __restrict__ out)
{
    __shared__ ull   sUV [42 * SPS];    // packed (u, v) input rows
    __shared__ ull   sH01[42 * SHS];    // packed (hu, hv)
    __shared__ ull   sH23[42 * SHS];    // packed (hu2, hv2)
    __shared__ float warpsum[8];
    __shared__ bool  is_last;

    const int tid = threadIdx.x;
    const int bx = blockIdx.x, by = blockIdx.y, bz = blockIdx.z;

    const float* __restrict__ p = pred + (size_t)bz * (IMG_H * IMG_W);
    const float* __restrict__ q = targ + (size_t)bz * (IMG_H * IMG_W);

    const int gx0 = bx * TW - 5;
    const int ybase = by * (CHUNK * NCHUNK);
    const bool xin = (gx0 >= 0) && (gx0 + INW <= IMG_W);

    float local = 0.f;

    for (int ch = 0; ch < NCHUNK; ch++) {
        const int nrows = (ch == 0) ? 42 : 32;
        const int gyb   = (ch == 0) ? (ybase - 5) : (ybase + ch * CHUNK + 5);
        const int hdst0 = (ch == 0) ? 0 : 10;

        __syncthreads();   // prior V-pass / H reads complete

        // ---- roll sH: rows 32..41 -> 0..9 ----
        if (ch > 0) {
            for (int i = tid; i < 10 * TW; i += 256) {
                int r = i >> 5, c = i & 31;
                int d = r * SHS + c, s = (32 + r) * SHS + c;
                sH01[d] = sH01[s];
                sH23[d] = sH23[s];
            }
        }

        // ---- load new input rows as packed (u,v), interior fast path ----
        if (xin && gyb >= 0 && gyb + nrows <= IMG_H) {
            const float* pb = p + gyb * IMG_W + gx0;
            const float* qb = q + gyb * IMG_W + gx0;
            for (int i = tid; i < nrows * INW; i += 256) {
                int r = i / INW, c = i - r * INW;
                int o = r * IMG_W + c;
                float pv = pb[o], qv = qb[o];
                sUV[r * SPS + c] = pack2(pv + qv, pv - qv);
            }
        } else {
            for (int i = tid; i < nrows * INW; i += 256) {
                int r = i / INW, c = i - r * INW;
                int gy = gyb + r, gx = gx0 + c;
                float pv = 0.f, qv = 0.f;
                if ((unsigned)gy < IMG_H && (unsigned)gx < IMG_W) {
                    int o = gy * IMG_W + gx;
                    pv = p[o]; qv = q[o];
                }
                sUV[r * SPS + c] = pack2(pv + qv, pv - qv);
            }
        }
        __syncthreads();

        // ---- horizontal pass ----
        // lane map: r = 4*(t>>5) + (t&3), cg = ((t&31)>>2)*4  (conflict-free LDS.64)
        const int ntask = ((nrows + 3) >> 2) << 5;   // 256 (steady) or 352 (ch 0)
        for (int t = tid; t < ntask; t += 256) {
            int r  = ((t >> 5) << 2) + (t & 3);
            if (r >= nrows) continue;
            int cg = (t & 31) & ~3;                  // 0,4,...,28

            ull a01[4], a23[4];
            #pragma unroll
            for (int k = 0; k < 4; k++) { a01[k] = 0; a23[k] = 0; }

            const ull* rp = sUV + r * SPS + cg;
            #pragma unroll
            for (int j = 0; j < 14; j++) {
                ull uv = rp[j];
                ull sq = mul2(uv, uv);               // (u*u, v*v)
                #pragma unroll
                for (int k = 0; k < 4; k++) {
                    int tap = j - k;
                    if (tap >= 0 && tap < 11) {
                        ull w2 = W2(tap);
                        a01[k] = fma2(w2, uv, a01[k]);
                        a23[k] = fma2(w2, sq, a23[k]);
                    }
                }
            }
            int hb = (hdst0 + r) * SHS + cg;
            #pragma unroll
            for (int k = 0; k < 4; k++) {
                sH01[hb + k] = a01[k];
                sH23[hb + k] = a23[k];
            }
        }
        __syncthreads();

        // ---- vertical pass + SSIM pointwise: thread -> 4 rows of one col ----
        {
            const int tx = tid & 31;
            const int y0 = (tid >> 5) << 2;          // 0,4,...,28

            ull acc01[4], acc23[4];
            #pragma unroll
            for (int k = 0; k < 4; k++) { acc01[k] = 0; acc23[k] = 0; }

            #pragma unroll
            for (int jj = 0; jj < 14; jj++) {
                int rb = (y0 + jj) * SHS + tx;
                ull v01 = sH01[rb];
                ull v23 = sH23[rb];
                #pragma unroll
                for (int k = 0; k < 4; k++) {
                    int tap = jj - k;
                    if (tap >= 0 && tap < 11) {
                        ull w2 = W2(tap);
                        acc01[k] = fma2(w2, v01, acc01[k]);
                        acc23[k] = fma2(w2, v23, acc23[k]);
                    }
                }
            }

            const float C1 = 1e-4f, C2 = 9e-4f;
            #pragma unroll
            for (int k = 0; k < 4; k++) {
                float2 m = unpack2(acc01[k]);        // (mu_u, mu_v)
                float2 e = unpack2(acc23[k]);        // (E[u^2], E[v^2])
                float mu2 = m.x * m.x;
                float mv2 = m.y * m.y;
                float su  = e.x - mu2;               // sigma_u
                float sv  = e.y - mv2;               // sigma_v
                float num = (0.5f * (mu2 - mv2) + C1) * (0.5f * (su - sv) + C2);
                float den = (0.5f * (mu2 + mv2) + C1) * (0.5f * (su + sv) + C2);
                local += __fdividef(num, den);
            }
        }
    }

    // ---- block reduction ----
    #pragma unroll
    for (int o = 16; o > 0; o >>= 1)
        local += __shfl_down_sync(0xFFFFFFFFu, local, o);
    if ((tid & 31) == 0) warpsum[tid >> 5] = local;
    __syncthreads();
    if (tid == 0) {
        float s = 0.f;
        #pragma unroll
        for (int i = 0; i < 8; i++) s += warpsum[i];
        g_part[(bz * GYB + by) * GXB + bx] = s;
        __threadfence();
        unsigned old = atomicAdd(&g_count, 1u);
        is_last = (old == NPART - 1);
    }
    __syncthreads();

    // ---- last block: deterministic fixed-order final reduction ----
    if (is_last) {
        double s = 0.0;
        for (int i = tid; i < NPART; i += 256)
            s += (double)__ldcg(&g_part[i]);
        double* sd = (double*)sUV;     // reuse smem (tile phase done)
        sd[tid] = s;
        __syncthreads();
        for (int o = 128; o > 0; o >>= 1) {
            if (tid < o) sd[tid] += sd[tid + o];
            __syncthreads();
        }
        if (tid == 0) {
            out[0] = (float)(1.0 - sd[0] / NPIX);
            g_count = 0;               // reset for next replay
        }
    }
}

extern "C" void kernel_launch(void* const* d_in, const int* in_sizes, int n_in,
                              void* d_out, int out_size)
{
    const float* pred = (const float*)d_in[0];
    const float* targ = (const float*)d_in[1];
    float* out = (float*)d_out;

    dim3 grid(GXB, GYB, NCH);   // 16 x-strips, 2 y-halves, 48 channel-images
    ssim_strip_kernel<<<grid, 256>>>(pred, targ, out);
}